// round 11
// baseline (speedup 1.0000x reference)
#include <cuda_runtime.h>

#define NN 100000
#define EE 800000
#define DD 64

#define SCAT_BLOCKS 296    // grid-stride scatter part of fused kernel
#define GEMM_BLOCKS 592    // grid-stride gemm (4/SM)
#define AGG_BLOCKS  1184   // grid-stride agg (8/SM, one wave)
#define HIST_BLOCKS 296

// Scratch (allocation-free rule: __device__ globals)
__device__ float g_g[NN * DD];      // g = dis * (x @ W)
__device__ float g_x[NN * DD];      // ping-pong x between rounds
__device__ int   g_deg[NN];
__device__ int   g_rowptr[NN + 1];
__device__ int   g_cursor[NN];
__device__ int   g_col[EE];
__device__ float g_dis[NN];

// ---------------- CSR build ----------------

__global__ void k_hist(const int* __restrict__ dst, int e) {
    int stride = gridDim.x * blockDim.x;
    for (int i = blockIdx.x * blockDim.x + threadIdx.x; i < e; i += stride)
        atomicAdd(&g_deg[dst[i]], 1);
}

// Single-block exclusive scan; dis = rsqrt(deg+1); re-zeroes g_deg so the
// next launch's k_hist starts from zero (static init -> replay-identical).
__global__ void k_scan(int n) {
    __shared__ int part[1024];
    int t = threadIdx.x;
    int C = (n + 1023) / 1024;
    int lo = t * C;
    int hi = min(lo + C, n);
    int s = 0;
    for (int i = lo; i < hi; i++) s += g_deg[i];
    part[t] = s;
    __syncthreads();
    for (int off = 1; off < 1024; off <<= 1) {
        int v = (t >= off) ? part[t - off] : 0;
        __syncthreads();
        part[t] += v;
        __syncthreads();
    }
    int run = (t == 0) ? 0 : part[t - 1];
    for (int i = lo; i < hi; i++) {
        int d = g_deg[i];
        g_deg[i] = 0;
        g_rowptr[i] = run;
        g_cursor[i] = run;
        g_dis[i] = rsqrtf((float)(d + 1));   // +1 self-loop
        run += d;
    }
    if (t == 1023) g_rowptr[n] = run;
}

// ---------------- GEMM core (grid-stride over 64-row tiles) ----------------

__device__ __forceinline__ void gemm_tiles_loop(const float* __restrict__ x,
                                                const float* __restrict__ W,
                                                int n, int tile0, int tile_stride,
                                                float* Wsh, float* Xsh, int t) {
    // Load W once per CTA
    {
        const float4* W4 = (const float4*)W;
        float4* Ws4 = (float4*)Wsh;
        #pragma unroll
        for (int i = t; i < 1024; i += 256) Ws4[i] = W4[i];
    }

    int ntiles = (n + 63) / 64;
    int tx = t & 15;
    int ty = t >> 4;

    for (int tile = tile0; tile < ntiles; tile += tile_stride) {
        int rowbase = tile * 64;
        __syncthreads();   // Wsh ready (1st iter) / prev readers done (later iters)
        {
            float4* Xs4 = (float4*)Xsh;
            #pragma unroll
            for (int i = t; i < 1024; i += 256) {
                int r = i >> 4, k4 = i & 15;
                float4 v = make_float4(0.f, 0.f, 0.f, 0.f);
                if (rowbase + r < n)
                    v = ((const float4*)(x + (size_t)(rowbase + r) * DD))[k4];
                Xs4[i] = v;
            }
        }
        __syncthreads();

        float acc[4][4];
        #pragma unroll
        for (int i = 0; i < 4; i++)
            #pragma unroll
            for (int j = 0; j < 4; j++) acc[i][j] = 0.f;

        #pragma unroll 8
        for (int k = 0; k < 64; k++) {
            float4 w = ((const float4*)(Wsh + k * DD))[tx];
            float a0 = Xsh[(ty * 4 + 0) * DD + k];
            float a1 = Xsh[(ty * 4 + 1) * DD + k];
            float a2 = Xsh[(ty * 4 + 2) * DD + k];
            float a3 = Xsh[(ty * 4 + 3) * DD + k];
            acc[0][0] += a0 * w.x; acc[0][1] += a0 * w.y; acc[0][2] += a0 * w.z; acc[0][3] += a0 * w.w;
            acc[1][0] += a1 * w.x; acc[1][1] += a1 * w.y; acc[1][2] += a1 * w.z; acc[1][3] += a1 * w.w;
            acc[2][0] += a2 * w.x; acc[2][1] += a2 * w.y; acc[2][2] += a2 * w.z; acc[2][3] += a2 * w.w;
            acc[3][0] += a3 * w.x; acc[3][1] += a3 * w.y; acc[3][2] += a3 * w.z; acc[3][3] += a3 * w.w;
        }

        #pragma unroll
        for (int i = 0; i < 4; i++) {
            int r = rowbase + ty * 4 + i;
            if (r < n) {
                float d = g_dis[r];
                float4 o = make_float4(acc[i][0] * d, acc[i][1] * d, acc[i][2] * d, acc[i][3] * d);
                ((float4*)(g_g + (size_t)r * DD))[tx] = o;
            }
        }
    }
}

// Fused: blocks [0, SCAT_BLOCKS) grid-stride the CSR scatter; the rest
// grid-stride the round-0 GEMM. Independent outputs; both depend on k_scan.
__global__ __launch_bounds__(256) void k_scatter_gemm(const int* __restrict__ src,
                                                      const int* __restrict__ dst, int e,
                                                      const float* __restrict__ x,
                                                      const float* __restrict__ W, int n) {
    __shared__ float Wsh[DD * DD];
    __shared__ float Xsh[DD * DD];

    if (blockIdx.x < SCAT_BLOCKS) {
        int stride = SCAT_BLOCKS * 256;
        for (int i = blockIdx.x * 256 + threadIdx.x; i < e; i += stride) {
            int d = dst[i];
            int pos = atomicAdd(&g_cursor[d], 1);
            g_col[pos] = src[i];
        }
        return;
    }
    gemm_tiles_loop(x, W, n, blockIdx.x - SCAT_BLOCKS, GEMM_BLOCKS,
                    Wsh, Xsh, threadIdx.x);
}

// Standalone grid-stride GEMM for rounds 1..3
__global__ __launch_bounds__(256) void k_gemm(const float* __restrict__ x,
                                              const float* __restrict__ W, int n) {
    __shared__ float Wsh[DD * DD];
    __shared__ float Xsh[DD * DD];
    gemm_tiles_loop(x, W, n, blockIdx.x, GEMM_BLOCKS, Wsh, Xsh, threadIdx.x);
}

// Warp per node, GRID-STRIDE over nodes (one wave of CTAs; each warp loops
// ~10 nodes, overlapping consecutive nodes' latency chains).
//   agg[v] = dis[v] * (sum_{u->v} g[u] + g[v]) + b, then LayerNorm -> out
__global__ __launch_bounds__(256) void k_agg_ln(const float* __restrict__ b,
                                                const float* __restrict__ gamma,
                                                const float* __restrict__ beta,
                                                float* __restrict__ out, int n) {
    int gwarp  = (blockIdx.x * blockDim.x + threadIdx.x) >> 5;
    int nwarps = (gridDim.x * blockDim.x) >> 5;
    int lane   = threadIdx.x & 31;

    const float2* g2 = (const float2*)g_g;
    float2 bb = ((const float2*)b)[lane];
    float2 gm = ((const float2*)gamma)[lane];
    float2 bt = ((const float2*)beta)[lane];

    for (int v = gwarp; v < n; v += nwarps) {
        float dv = g_dis[v];
        int rp0 = g_rowptr[v];
        int rp1 = g_rowptr[v + 1];
        float2 acc = g2[(size_t)v * 32 + lane];   // self-loop g[v]

        for (int base = rp0; base < rp1; base += 32) {
            int j = base + lane;
            int c = (j < rp1) ? g_col[j] : 0;
            int cnt = min(32, rp1 - base);
            int jj = 0;
            for (; jj + 4 <= cnt; jj += 4) {
                int u0 = __shfl_sync(0xffffffffu, c, jj + 0);
                int u1 = __shfl_sync(0xffffffffu, c, jj + 1);
                int u2 = __shfl_sync(0xffffffffu, c, jj + 2);
                int u3 = __shfl_sync(0xffffffffu, c, jj + 3);
                float2 m0 = g2[(size_t)u0 * 32 + lane];
                float2 m1 = g2[(size_t)u1 * 32 + lane];
                float2 m2 = g2[(size_t)u2 * 32 + lane];
                float2 m3 = g2[(size_t)u3 * 32 + lane];
                acc.x += (m0.x + m1.x) + (m2.x + m3.x);
                acc.y += (m0.y + m1.y) + (m2.y + m3.y);
            }
            for (; jj < cnt; jj++) {
                int u = __shfl_sync(0xffffffffu, c, jj);
                float2 m = g2[(size_t)u * 32 + lane];
                acc.x += m.x;
                acc.y += m.y;
            }
        }

        float a0 = acc.x * dv + bb.x;
        float a1 = acc.y * dv + bb.y;

        float s  = a0 + a1;
        float ss = a0 * a0 + a1 * a1;
        #pragma unroll
        for (int o = 16; o > 0; o >>= 1) {
            s  += __shfl_xor_sync(0xffffffffu, s, o);
            ss += __shfl_xor_sync(0xffffffffu, ss, o);
        }
        float mu  = s * (1.f / 64.f);
        float var = ss * (1.f / 64.f) - mu * mu;
        float inv = rsqrtf(var + 1e-5f);

        float2 o2;
        o2.x = (a0 - mu) * inv * gm.x + bt.x;
        o2.y = (a1 - mu) * inv * gm.y + bt.y;
        ((float2*)out)[(size_t)v * 32 + lane] = o2;
    }
}

// ---------------- launch ----------------

extern "C" void kernel_launch(void* const* d_in, const int* in_sizes, int n_in,
                              void* d_out, int out_size) {
    const float* x     = (const float*)d_in[0];
    const int*   ei    = (const int*)d_in[1];
    const float* W     = (const float*)d_in[2];
    const float* b     = (const float*)d_in[3];
    const float* gamma = (const float*)d_in[4];
    const float* beta  = (const float*)d_in[5];

    int n = in_sizes[0] / DD;      // 100000
    int e = in_sizes[1] / 2;       // 800000
    const int* src = ei;
    const int* dst = ei + e;

    k_hist<<<HIST_BLOCKS, 256>>>(dst, e);                             // kernel 1
    k_scan<<<1, 1024>>>(n);                                           // kernel 2
    k_scatter_gemm<<<SCAT_BLOCKS + GEMM_BLOCKS, 256>>>(               // kernel 3
        src, dst, e, x, W, n);

    const int NUM_ROUNDS = 4;
    for (int r = 0; r < NUM_ROUNDS; r++) {
        if (r > 0)
            k_gemm<<<GEMM_BLOCKS, 256>>>((const float*)g_x, W, n);
        float* xout = (r == NUM_ROUNDS - 1) ? (float*)d_out : g_x;
        k_agg_ln<<<AGG_BLOCKS, 256>>>(b, gamma, beta, xout, n);       // kernel 4 on r=0 -> PROFILED
    }
}

// round 12
// speedup vs baseline: 1.2700x; 1.2700x over previous
#include <cuda_runtime.h>

#define NN 100000
#define EE 800000
#define DD 64

#define SCATTER_BLOCKS 3125   // ceil(EE/256)
#define GEMM_BLOCKS    1563   // ceil(NN/64)

// Scratch (allocation-free rule: __device__ globals)
__device__ float g_g[NN * DD];      // g = dis * (x @ W)
__device__ float g_x[NN * DD];      // ping-pong x between rounds
__device__ int   g_deg[NN];
__device__ int   g_rowptr[NN + 1];
__device__ int   g_cursor[NN];
__device__ int   g_col[EE];
__device__ float g_dis[NN];

// ---------------- CSR build ----------------

__global__ void k_hist(const int* __restrict__ dst, int e) {
    int i = blockIdx.x * blockDim.x + threadIdx.x;
    if (i < e) atomicAdd(&g_deg[dst[i]], 1);
}

// Single-block scan, COALESCED: each warp owns a contiguous chunk; lanes
// stride by 32 so every memory instruction hits 1 cache line (vs 32 before).
// Also: dis = rsqrt(deg+1); re-zeroes g_deg for the next launch.
__global__ __launch_bounds__(1024) void k_scan(int n) {
    __shared__ int s_tot[32];
    __shared__ int s_base[32];

    int t    = threadIdx.x;
    int w    = t >> 5;
    int lane = t & 31;
    int chunk = (n + 31) / 32 / 32 * 32;      // per-warp chunk, mult of 32
    // ensure full coverage: round chunk so 32*chunk >= n
    if (chunk * 32 < n) chunk += 32;
    int lo = w * chunk;
    int hi = min(lo + chunk, n);

    // Pass 1: warp sum over its chunk (coalesced)
    int s = 0;
    for (int i = lo + lane; i < hi; i += 32) s += g_deg[i];
    #pragma unroll
    for (int o = 16; o > 0; o >>= 1) s += __shfl_xor_sync(0xffffffffu, s, o);
    if (lane == 0) s_tot[w] = s;
    __syncthreads();

    // Warp 0: exclusive scan of 32 warp totals
    if (w == 0) {
        int v = s_tot[lane];
        int x = v;
        #pragma unroll
        for (int o = 1; o < 32; o <<= 1) {
            int y = __shfl_up_sync(0xffffffffu, x, o);
            if (lane >= o) x += y;
        }
        s_base[lane] = x - v;    // exclusive base for warp `lane`
    }
    __syncthreads();

    // Pass 2: per-32-chunk inclusive shfl-scan, coalesced loads/stores
    int run = s_base[w];
    for (int start = lo; start < hi; start += 32) {
        int i = start + lane;
        bool valid = (i < hi);
        int v = valid ? g_deg[i] : 0;
        int x = v;
        #pragma unroll
        for (int o = 1; o < 32; o <<= 1) {
            int y = __shfl_up_sync(0xffffffffu, x, o);
            if (lane >= o) x += y;
        }
        int excl = run + x - v;
        if (valid) {
            g_rowptr[i] = excl;
            g_cursor[i] = excl;
            g_dis[i]    = rsqrtf((float)(v + 1));   // +1 self-loop
            g_deg[i]    = 0;                        // reset for next launch
        }
        run += __shfl_sync(0xffffffffu, x, 31);     // chunk total
    }

    // total edges = base of last warp + its chunk sum; last warp's `run`
    // ends at exactly that value.
    if (hi == n && lane == 31) g_rowptr[n] = run;   // the warp that owns the end
    // (if n < 32*chunk the owning warp is the one with hi==n; others skip)
}

// ---------------- GEMM core (shared by fused + standalone kernels) ----------------

__device__ __forceinline__ void gemm_tile(const float* __restrict__ x,
                                          const float* __restrict__ W,
                                          int rowbase, int n,
                                          float* Wsh, float* Xsh, int t) {
    {
        const float4* W4 = (const float4*)W;
        float4* Ws4 = (float4*)Wsh;
        #pragma unroll
        for (int i = t; i < 1024; i += 256) Ws4[i] = W4[i];
    }
    {
        float4* Xs4 = (float4*)Xsh;
        #pragma unroll
        for (int i = t; i < 1024; i += 256) {
            int r = i >> 4, k4 = i & 15;
            float4 v = make_float4(0.f, 0.f, 0.f, 0.f);
            if (rowbase + r < n)
                v = ((const float4*)(x + (size_t)(rowbase + r) * DD))[k4];
            Xs4[i] = v;
        }
    }
    __syncthreads();

    int tx = t & 15;
    int ty = t >> 4;

    float acc[4][4];
    #pragma unroll
    for (int i = 0; i < 4; i++)
        #pragma unroll
        for (int j = 0; j < 4; j++) acc[i][j] = 0.f;

    #pragma unroll 8
    for (int k = 0; k < 64; k++) {
        float4 w = ((const float4*)(Wsh + k * DD))[tx];
        float a0 = Xsh[(ty * 4 + 0) * DD + k];
        float a1 = Xsh[(ty * 4 + 1) * DD + k];
        float a2 = Xsh[(ty * 4 + 2) * DD + k];
        float a3 = Xsh[(ty * 4 + 3) * DD + k];
        acc[0][0] += a0 * w.x; acc[0][1] += a0 * w.y; acc[0][2] += a0 * w.z; acc[0][3] += a0 * w.w;
        acc[1][0] += a1 * w.x; acc[1][1] += a1 * w.y; acc[1][2] += a1 * w.z; acc[1][3] += a1 * w.w;
        acc[2][0] += a2 * w.x; acc[2][1] += a2 * w.y; acc[2][2] += a2 * w.z; acc[2][3] += a2 * w.w;
        acc[3][0] += a3 * w.x; acc[3][1] += a3 * w.y; acc[3][2] += a3 * w.z; acc[3][3] += a3 * w.w;
    }

    #pragma unroll
    for (int i = 0; i < 4; i++) {
        int r = rowbase + ty * 4 + i;
        if (r < n) {
            float d = g_dis[r];
            float4 o = make_float4(acc[i][0] * d, acc[i][1] * d, acc[i][2] * d, acc[i][3] * d);
            ((float4*)(g_g + (size_t)r * DD))[tx] = o;
        }
    }
}

// Fused: blocks [0, SCATTER_BLOCKS) do CSR scatter; the rest do round-0 GEMM.
__global__ __launch_bounds__(256) void k_scatter_gemm(const int* __restrict__ src,
                                                      const int* __restrict__ dst, int e,
                                                      const float* __restrict__ x,
                                                      const float* __restrict__ W, int n) {
    __shared__ float Wsh[DD * DD];
    __shared__ float Xsh[DD * DD];

    if (blockIdx.x < SCATTER_BLOCKS) {
        int i = blockIdx.x * 256 + threadIdx.x;
        if (i < e) {
            int d = dst[i];
            int pos = atomicAdd(&g_cursor[d], 1);
            g_col[pos] = src[i];
        }
        return;
    }
    int rowbase = (blockIdx.x - SCATTER_BLOCKS) * 64;
    gemm_tile(x, W, rowbase, n, Wsh, Xsh, threadIdx.x);
}

// Standalone GEMM for rounds 1..3
__global__ __launch_bounds__(256) void k_gemm(const float* __restrict__ x,
                                              const float* __restrict__ W, int n) {
    __shared__ float Wsh[DD * DD];
    __shared__ float Xsh[DD * DD];
    gemm_tile(x, W, blockIdx.x * 64, n, Wsh, Xsh, threadIdx.x);
}

// Warp per node (R10-measured kernel):
//   agg[v] = dis[v] * (sum_{u->v} g[u] + g[v]) + b, then LayerNorm -> out
__global__ __launch_bounds__(256) void k_agg_ln(const float* __restrict__ b,
                                                const float* __restrict__ gamma,
                                                const float* __restrict__ beta,
                                                float* __restrict__ out, int n) {
    int v    = (blockIdx.x * blockDim.x + threadIdx.x) >> 5;
    int lane = threadIdx.x & 31;
    if (v >= n) return;

    const float2* g2 = (const float2*)g_g;
    float dv = g_dis[v];
    float2 acc = g2[(size_t)v * 32 + lane];   // self-loop g[v]

    int rp0 = g_rowptr[v];
    int rp1 = g_rowptr[v + 1];
    for (int base = rp0; base < rp1; base += 32) {
        int j = base + lane;
        int c = (j < rp1) ? g_col[j] : 0;
        int cnt = min(32, rp1 - base);
        int jj = 0;
        for (; jj + 4 <= cnt; jj += 4) {
            int u0 = __shfl_sync(0xffffffffu, c, jj + 0);
            int u1 = __shfl_sync(0xffffffffu, c, jj + 1);
            int u2 = __shfl_sync(0xffffffffu, c, jj + 2);
            int u3 = __shfl_sync(0xffffffffu, c, jj + 3);
            float2 m0 = g2[(size_t)u0 * 32 + lane];
            float2 m1 = g2[(size_t)u1 * 32 + lane];
            float2 m2 = g2[(size_t)u2 * 32 + lane];
            float2 m3 = g2[(size_t)u3 * 32 + lane];
            acc.x += (m0.x + m1.x) + (m2.x + m3.x);
            acc.y += (m0.y + m1.y) + (m2.y + m3.y);
        }
        for (; jj < cnt; jj++) {
            int u = __shfl_sync(0xffffffffu, c, jj);
            float2 m = g2[(size_t)u * 32 + lane];
            acc.x += m.x;
            acc.y += m.y;
        }
    }

    float2 bb = ((const float2*)b)[lane];
    float a0 = acc.x * dv + bb.x;
    float a1 = acc.y * dv + bb.y;

    // LayerNorm over 64 features (2 per lane)
    float s  = a0 + a1;
    float ss = a0 * a0 + a1 * a1;
    #pragma unroll
    for (int o = 16; o > 0; o >>= 1) {
        s  += __shfl_xor_sync(0xffffffffu, s, o);
        ss += __shfl_xor_sync(0xffffffffu, ss, o);
    }
    float mu  = s * (1.f / 64.f);
    float var = ss * (1.f / 64.f) - mu * mu;
    float inv = rsqrtf(var + 1e-5f);

    float2 gm = ((const float2*)gamma)[lane];
    float2 bt = ((const float2*)beta)[lane];
    float2 o2;
    o2.x = (a0 - mu) * inv * gm.x + bt.x;
    o2.y = (a1 - mu) * inv * gm.y + bt.y;
    ((float2*)out)[(size_t)v * 32 + lane] = o2;
}

// ---------------- launch ----------------

extern "C" void kernel_launch(void* const* d_in, const int* in_sizes, int n_in,
                              void* d_out, int out_size) {
    const float* x     = (const float*)d_in[0];
    const int*   ei    = (const int*)d_in[1];
    const float* W     = (const float*)d_in[2];
    const float* b     = (const float*)d_in[3];
    const float* gamma = (const float*)d_in[4];
    const float* beta  = (const float*)d_in[5];

    int n = in_sizes[0] / DD;      // 100000
    int e = in_sizes[1] / 2;       // 800000
    const int* src = ei;
    const int* dst = ei + e;

    k_hist<<<(e + 255) / 256, 256>>>(dst, e);                       // kernel 1
    k_scan<<<1, 1024>>>(n);                                         // kernel 2 (NEW: coalesced)
    k_scatter_gemm<<<SCATTER_BLOCKS + GEMM_BLOCKS, 256>>>(          // kernel 3
        src, dst, e, x, W, n);

    int agg_blocks = (n + 7) / 8;   // warp per node, 8 warps/block

    const int NUM_ROUNDS = 4;
    for (int r = 0; r < NUM_ROUNDS; r++) {
        if (r > 0)
            k_gemm<<<GEMM_BLOCKS, 256>>>((const float*)g_x, W, n);
        float* xout = (r == NUM_ROUNDS - 1) ? (float*)d_out : g_x;
        k_agg_ln<<<agg_blocks, 256>>>(b, gamma, beta, xout, n);     // launch 6 = agg r1 -> PROFILED
    }
}

// round 13
// speedup vs baseline: 1.2720x; 1.0015x over previous
#include <cuda_runtime.h>
#include <cuda_fp16.h>

#define NN 100000
#define EE 800000
#define DD 64

#define SCATTER_BLOCKS 3125   // ceil(EE/256)
#define GEMM_BLOCKS    1563   // ceil(NN/64)

// Scratch (allocation-free rule: __device__ globals)
// g stored as fp16 pairs: row = 32 x uint32 (half2) = 128 bytes
__device__ unsigned g_h[NN * 32];
__device__ float g_x[NN * DD];      // ping-pong x between rounds (fp32)
__device__ int   g_deg[NN];
__device__ int   g_rowptr[NN + 1];
__device__ int   g_cursor[NN];
__device__ int   g_col[EE];
__device__ float g_dis[NN];

// ---------------- CSR build ----------------

__global__ void k_hist(const int* __restrict__ dst, int e) {
    int i = blockIdx.x * blockDim.x + threadIdx.x;
    if (i < e) atomicAdd(&g_deg[dst[i]], 1);
}

// Single-block coalesced scan (R12-proven); dis = rsqrt(deg+1); re-zeroes deg.
__global__ __launch_bounds__(1024) void k_scan(int n) {
    __shared__ int s_tot[32];
    __shared__ int s_base[32];

    int t    = threadIdx.x;
    int w    = t >> 5;
    int lane = t & 31;
    int chunk = (n + 31) / 32 / 32 * 32;
    if (chunk * 32 < n) chunk += 32;
    int lo = w * chunk;
    int hi = min(lo + chunk, n);

    int s = 0;
    for (int i = lo + lane; i < hi; i += 32) s += g_deg[i];
    #pragma unroll
    for (int o = 16; o > 0; o >>= 1) s += __shfl_xor_sync(0xffffffffu, s, o);
    if (lane == 0) s_tot[w] = s;
    __syncthreads();

    if (w == 0) {
        int v = s_tot[lane];
        int x = v;
        #pragma unroll
        for (int o = 1; o < 32; o <<= 1) {
            int y = __shfl_up_sync(0xffffffffu, x, o);
            if (lane >= o) x += y;
        }
        s_base[lane] = x - v;
    }
    __syncthreads();

    int run = s_base[w];
    for (int start = lo; start < hi; start += 32) {
        int i = start + lane;
        bool valid = (i < hi);
        int v = valid ? g_deg[i] : 0;
        int x = v;
        #pragma unroll
        for (int o = 1; o < 32; o <<= 1) {
            int y = __shfl_up_sync(0xffffffffu, x, o);
            if (lane >= o) x += y;
        }
        int excl = run + x - v;
        if (valid) {
            g_rowptr[i] = excl;
            g_cursor[i] = excl;
            g_dis[i]    = rsqrtf((float)(v + 1));
            g_deg[i]    = 0;
        }
        run += __shfl_sync(0xffffffffu, x, 31);
    }
    if (hi == n && lane == 31) g_rowptr[n] = run;
}

// ---------------- GEMM core: writes fp16-packed g ----------------

__device__ __forceinline__ void gemm_tile(const float* __restrict__ x,
                                          const float* __restrict__ W,
                                          int rowbase, int n,
                                          float* Wsh, float* Xsh, int t) {
    {
        const float4* W4 = (const float4*)W;
        float4* Ws4 = (float4*)Wsh;
        #pragma unroll
        for (int i = t; i < 1024; i += 256) Ws4[i] = W4[i];
    }
    {
        float4* Xs4 = (float4*)Xsh;
        #pragma unroll
        for (int i = t; i < 1024; i += 256) {
            int r = i >> 4, k4 = i & 15;
            float4 v = make_float4(0.f, 0.f, 0.f, 0.f);
            if (rowbase + r < n)
                v = ((const float4*)(x + (size_t)(rowbase + r) * DD))[k4];
            Xs4[i] = v;
        }
    }
    __syncthreads();

    int tx = t & 15;
    int ty = t >> 4;

    float acc[4][4];
    #pragma unroll
    for (int i = 0; i < 4; i++)
        #pragma unroll
        for (int j = 0; j < 4; j++) acc[i][j] = 0.f;

    #pragma unroll 8
    for (int k = 0; k < 64; k++) {
        float4 w = ((const float4*)(Wsh + k * DD))[tx];
        float a0 = Xsh[(ty * 4 + 0) * DD + k];
        float a1 = Xsh[(ty * 4 + 1) * DD + k];
        float a2 = Xsh[(ty * 4 + 2) * DD + k];
        float a3 = Xsh[(ty * 4 + 3) * DD + k];
        acc[0][0] += a0 * w.x; acc[0][1] += a0 * w.y; acc[0][2] += a0 * w.z; acc[0][3] += a0 * w.w;
        acc[1][0] += a1 * w.x; acc[1][1] += a1 * w.y; acc[1][2] += a1 * w.z; acc[1][3] += a1 * w.w;
        acc[2][0] += a2 * w.x; acc[2][1] += a2 * w.y; acc[2][2] += a2 * w.z; acc[2][3] += a2 * w.w;
        acc[3][0] += a3 * w.x; acc[3][1] += a3 * w.y; acc[3][2] += a3 * w.z; acc[3][3] += a3 * w.w;
    }

    #pragma unroll
    for (int i = 0; i < 4; i++) {
        int r = rowbase + ty * 4 + i;
        if (r < n) {
            float d = g_dis[r];
            __half2 p0 = __floats2half2_rn(acc[i][0] * d, acc[i][1] * d);
            __half2 p1 = __floats2half2_rn(acc[i][2] * d, acc[i][3] * d);
            uint2 o;
            o.x = *reinterpret_cast<unsigned*>(&p0);
            o.y = *reinterpret_cast<unsigned*>(&p1);
            ((uint2*)(g_h + (size_t)r * 32))[tx] = o;   // cols tx*4..tx*4+3
        }
    }
}

// Fused: blocks [0, SCATTER_BLOCKS) do CSR scatter; the rest do round-0 GEMM.
__global__ __launch_bounds__(256) void k_scatter_gemm(const int* __restrict__ src,
                                                      const int* __restrict__ dst, int e,
                                                      const float* __restrict__ x,
                                                      const float* __restrict__ W, int n) {
    __shared__ float Wsh[DD * DD];
    __shared__ float Xsh[DD * DD];

    if (blockIdx.x < SCATTER_BLOCKS) {
        int i = blockIdx.x * 256 + threadIdx.x;
        if (i < e) {
            int d = dst[i];
            int pos = atomicAdd(&g_cursor[d], 1);
            g_col[pos] = src[i];
        }
        return;
    }
    int rowbase = (blockIdx.x - SCATTER_BLOCKS) * 64;
    gemm_tile(x, W, rowbase, n, Wsh, Xsh, threadIdx.x);
}

// Standalone GEMM for rounds 1..3
__global__ __launch_bounds__(256) void k_gemm(const float* __restrict__ x,
                                              const float* __restrict__ W, int n) {
    __shared__ float Wsh[DD * DD];
    __shared__ float Xsh[DD * DD];
    gemm_tile(x, W, blockIdx.x * 64, n, Wsh, Xsh, threadIdx.x);
}

// Warp per node; fp16 gather (one LDG.32 per edge = 128B row), fp32 accumulate:
//   agg[v] = dis[v] * (sum_{u->v} g[u] + g[v]) + b, then LayerNorm -> out
__global__ __launch_bounds__(256) void k_agg_ln(const float* __restrict__ b,
                                                const float* __restrict__ gamma,
                                                const float* __restrict__ beta,
                                                float* __restrict__ out, int n) {
    int v    = (blockIdx.x * blockDim.x + threadIdx.x) >> 5;
    int lane = threadIdx.x & 31;
    if (v >= n) return;

    const unsigned* gh = g_h;
    float dv = g_dis[v];

    // lane covers features 2*lane, 2*lane+1 (same mapping as fp32 float2 path)
    unsigned su = gh[(size_t)v * 32 + lane];
    __half2 sh = *reinterpret_cast<__half2*>(&su);
    float2 acc = __half22float2(sh);                  // self-loop g[v]

    int rp0 = g_rowptr[v];
    int rp1 = g_rowptr[v + 1];
    for (int base = rp0; base < rp1; base += 32) {
        int j = base + lane;
        int c = (j < rp1) ? g_col[j] : 0;
        int cnt = min(32, rp1 - base);
        int jj = 0;
        for (; jj + 4 <= cnt; jj += 4) {
            int u0 = __shfl_sync(0xffffffffu, c, jj + 0);
            int u1 = __shfl_sync(0xffffffffu, c, jj + 1);
            int u2 = __shfl_sync(0xffffffffu, c, jj + 2);
            int u3 = __shfl_sync(0xffffffffu, c, jj + 3);
            unsigned w0 = gh[(size_t)u0 * 32 + lane];
            unsigned w1 = gh[(size_t)u1 * 32 + lane];
            unsigned w2 = gh[(size_t)u2 * 32 + lane];
            unsigned w3 = gh[(size_t)u3 * 32 + lane];
            float2 m0 = __half22float2(*reinterpret_cast<__half2*>(&w0));
            float2 m1 = __half22float2(*reinterpret_cast<__half2*>(&w1));
            float2 m2 = __half22float2(*reinterpret_cast<__half2*>(&w2));
            float2 m3 = __half22float2(*reinterpret_cast<__half2*>(&w3));
            acc.x += (m0.x + m1.x) + (m2.x + m3.x);
            acc.y += (m0.y + m1.y) + (m2.y + m3.y);
        }
        for (; jj < cnt; jj++) {
            int u = __shfl_sync(0xffffffffu, c, jj);
            unsigned wv = gh[(size_t)u * 32 + lane];
            float2 m = __half22float2(*reinterpret_cast<__half2*>(&wv));
            acc.x += m.x;
            acc.y += m.y;
        }
    }

    float2 bb = ((const float2*)b)[lane];
    float a0 = acc.x * dv + bb.x;
    float a1 = acc.y * dv + bb.y;

    // LayerNorm over 64 features (2 per lane)
    float s  = a0 + a1;
    float ss = a0 * a0 + a1 * a1;
    #pragma unroll
    for (int o = 16; o > 0; o >>= 1) {
        s  += __shfl_xor_sync(0xffffffffu, s, o);
        ss += __shfl_xor_sync(0xffffffffu, ss, o);
    }
    float mu  = s * (1.f / 64.f);
    float var = ss * (1.f / 64.f) - mu * mu;
    float inv = rsqrtf(var + 1e-5f);

    float2 gm = ((const float2*)gamma)[lane];
    float2 bt = ((const float2*)beta)[lane];
    float2 o2;
    o2.x = (a0 - mu) * inv * gm.x + bt.x;
    o2.y = (a1 - mu) * inv * gm.y + bt.y;
    ((float2*)out)[(size_t)v * 32 + lane] = o2;
}

// ---------------- launch ----------------

extern "C" void kernel_launch(void* const* d_in, const int* in_sizes, int n_in,
                              void* d_out, int out_size) {
    const float* x     = (const float*)d_in[0];
    const int*   ei    = (const int*)d_in[1];
    const float* W     = (const float*)d_in[2];
    const float* b     = (const float*)d_in[3];
    const float* gamma = (const float*)d_in[4];
    const float* beta  = (const float*)d_in[5];

    int n = in_sizes[0] / DD;      // 100000
    int e = in_sizes[1] / 2;       // 800000
    const int* src = ei;
    const int* dst = ei + e;

    k_hist<<<(e + 255) / 256, 256>>>(dst, e);                       // kernel 1
    k_scan<<<1, 1024>>>(n);                                         // kernel 2
    k_scatter_gemm<<<SCATTER_BLOCKS + GEMM_BLOCKS, 256>>>(          // kernel 3
        src, dst, e, x, W, n);

    int agg_blocks = (n + 7) / 8;   // warp per node, 8 warps/block

    const int NUM_ROUNDS = 4;
    for (int r = 0; r < NUM_ROUNDS; r++) {
        if (r > 0)
            k_gemm<<<GEMM_BLOCKS, 256>>>((const float*)g_x, W, n);
        float* xout = (r == NUM_ROUNDS - 1) ? (float*)d_out : g_x;
        k_agg_ln<<<agg_blocks, 256>>>(b, gamma, beta, xout, n);
    }
}